// round 1
// baseline (speedup 1.0000x reference)
#include <cuda_runtime.h>
#include <cuda_bf16.h>
#include <cstdint>
#include <cstdio>

#define S 4096
#define GRID 128
#define BLOCK 512
#define NWARP (BLOCK / 32)                 // 16 warps
#define ROWS_PER_BLOCK (S / GRID)          // 32 rows, 2 per warp
#define CACHED_WARPS 11                    // 22 rows L1-pinned, 10 rows streamed (cg)

// ---------------- device-global scratch (no allocations allowed) ----------------
static __device__ __nv_bfloat16 g_M[(size_t)S * S];   // exp(log_trans), bf16, row-major
static __device__ float        g_w[2][S];             // ping-pong unnormalized filter
static __device__ float        g_partial[2][GRID];    // per-block partial sums of w
static __device__ unsigned     g_arrive;              // grid barrier counter

// ---------------- precompute: M = bf16(exp(log_trans)); reset barrier ----------------
__global__ void hmm_prep_kernel(const float* __restrict__ log_trans) {
    if (blockIdx.x == 0 && threadIdx.x == 0) g_arrive = 0u;
    const size_t n4 = (size_t)S * S / 4;
    const size_t stride = (size_t)gridDim.x * blockDim.x;
    for (size_t i = (size_t)blockIdx.x * blockDim.x + threadIdx.x; i < n4; i += stride) {
        float4 v = reinterpret_cast<const float4*>(log_trans)[i];
        __nv_bfloat162 lo, hi;
        lo.x = __float2bfloat16(__expf(v.x));
        lo.y = __float2bfloat16(__expf(v.y));
        hi.x = __float2bfloat16(__expf(v.z));
        hi.y = __float2bfloat16(__expf(v.w));
        reinterpret_cast<__nv_bfloat162*>(g_M)[2 * i]     = lo;
        reinterpret_cast<__nv_bfloat162*>(g_M)[2 * i + 1] = hi;
    }
}

// ---------------- helpers ----------------
__device__ __forceinline__ float warp_sum(float v) {
#pragma unroll
    for (int o = 16; o; o >>= 1) v += __shfl_xor_sync(0xffffffffu, v, o);
    return v;
}

// bf16 pair (packed in a u32) -> two exact f32
__device__ __forceinline__ float2 bfpair(unsigned u) {
    float2 r;
    r.x = __uint_as_float(u << 16);
    r.y = __uint_as_float(u & 0xffff0000u);
    return r;
}

__device__ __forceinline__ float fm8(uint4 a, float4 w0, float4 w1, float acc) {
    float2 p;
    p = bfpair(a.x); acc = fmaf(p.x, w0.x, acc); acc = fmaf(p.y, w0.y, acc);
    p = bfpair(a.y); acc = fmaf(p.x, w0.z, acc); acc = fmaf(p.y, w0.w, acc);
    p = bfpair(a.z); acc = fmaf(p.x, w1.x, acc); acc = fmaf(p.y, w1.y, acc);
    p = bfpair(a.w); acc = fmaf(p.x, w1.z, acc); acc = fmaf(p.y, w1.w, acc);
    return acc;
}

// Software grid barrier. release/acquire atomics only — NO __threadfence:
// gpu-scope fence emits CCTL.IVALL on sm_103a and would flush the L1-pinned
// M rows every step. Cross-block data is read via __ldcg (L2), so no
// L1 invalidation is ever needed on the consumer side.
__device__ __forceinline__ void grid_barrier(unsigned target) {
    __syncthreads();
    if (threadIdx.x == 0) {
        asm volatile("red.release.gpu.global.add.u32 [%0], %1;"
                     :: "l"(&g_arrive), "r"(1u) : "memory");
        unsigned v;
        do {
            asm volatile("ld.acquire.gpu.global.u32 %0, [%1];"
                         : "=r"(v) : "l"(&g_arrive) : "memory");
        } while (v < target);
    }
    __syncthreads();
}

// dot products of two adjacent rows against the smem-resident w vector
template <bool CACHED>
__device__ __forceinline__ void dot2(const uint4* __restrict__ A0,
                                     const float4* __restrict__ sw4,
                                     int lane, float& acc0, float& acc1) {
    const uint4* A1 = A0 + (S / 8);
#pragma unroll 4
    for (int kk = 0; kk < (S / 8) / 32; ++kk) {   // 16 iters
        int k = kk * 32 + lane;
        uint4 a0, a1;
        if (CACHED) {
            a0 = A0[k];
            a1 = A1[k];
        } else {
            float4 t0 = __ldcg(reinterpret_cast<const float4*>(A0) + k);
            float4 t1 = __ldcg(reinterpret_cast<const float4*>(A1) + k);
            a0 = *reinterpret_cast<uint4*>(&t0);
            a1 = *reinterpret_cast<uint4*>(&t1);
        }
        float4 w0 = sw4[2 * k];
        float4 w1 = sw4[2 * k + 1];
        acc0 = fm8(a0, w0, w1, acc0);
        acc1 = fm8(a1, w0, w1, acc1);
    }
}

// ---------------- persistent forward-filter kernel ----------------
__global__ void __launch_bounds__(BLOCK, 1) hmm_main_kernel(
    const float* __restrict__ log_M0,
    const float* __restrict__ log_emit,
    const int*   __restrict__ Tptr,
    float*       __restrict__ out)
{
    __shared__ float sw[S];          // current (unnormalized) filter, linear space
    __shared__ float s_red[NWARP];
    __shared__ float s_z;

    const int tid  = threadIdx.x;
    const int lane = tid & 31;
    const int warp = tid >> 5;
    const int bid  = blockIdx.x;
    const int T    = *Tptr;

    unsigned gen = 0;

    // ---- t = 0: w0 = exp(log_M0 + log_emit[0]) ----
    float local = 0.f;
    {
        int gi = bid * BLOCK + tid;
        if (gi < S) {
            float v = __expf(__ldcg(log_M0 + gi) + __ldcg(log_emit + gi));
            g_w[0][gi] = v;
            local = v;
        }
    }
    local = warp_sum(local);
    if (lane == 0) s_red[warp] = local;
    __syncthreads();
    if (warp == 0) {
        float v = (lane < NWARP) ? s_red[lane] : 0.f;
        v = warp_sum(v);
        if (lane == 0) g_partial[0][bid] = v;
    }
    ++gen;
    grid_barrier(gen * GRID);

    double lik = 0.0;
    float invZ;
    {   // Z0
        if (warp == 0) {
            float v = 0.f;
#pragma unroll
            for (int b = lane; b < GRID; b += 32) v += __ldcg(&g_partial[0][b]);
            v = warp_sum(v);
            if (lane == 0) s_z = v;
        }
        __syncthreads();
        float Z = s_z;
        invZ = 1.0f / Z;
        if (bid == 0 && tid == 0) lik += (double)logf(Z);
    }

    const int r0 = bid * ROWS_PER_BLOCK + warp * 2;
    const uint4*  A0  = reinterpret_cast<const uint4*>(g_M + (size_t)r0 * S);
    const float4* sw4 = reinterpret_cast<const float4*>(sw);

    for (int t = 1; t <= T; ++t) {
        const int cur = t & 1, prev = cur ^ 1;

        // broadcast previous (unnormalized) w into smem; 1/Z folded in epilogue
#pragma unroll
        for (int i = tid; i < S; i += BLOCK) sw[i] = __ldcg(&g_w[prev][i]);
        __syncthreads();

        float acc0 = 0.f, acc1 = 0.f;
        if (warp < CACHED_WARPS) dot2<true >(A0, sw4, lane, acc0, acc1);
        else                     dot2<false>(A0, sw4, lane, acc0, acc1);

        acc0 = warp_sum(acc0);
        acc1 = warp_sum(acc1);
        if (lane == 0) {
            const float* em = log_emit + (size_t)t * S + r0;
            float v0 = acc0 * __expf(__ldcg(em))     * invZ;
            float v1 = acc1 * __expf(__ldcg(em + 1)) * invZ;
            g_w[cur][r0]     = v0;
            g_w[cur][r0 + 1] = v1;
            s_red[warp] = v0 + v1;
        }
        __syncthreads();
        if (warp == 0) {
            float v = (lane < NWARP) ? s_red[lane] : 0.f;
            v = warp_sum(v);
            if (lane == 0) g_partial[cur][bid] = v;
        }
        ++gen;
        grid_barrier(gen * GRID);

        // everyone recomputes Z_t deterministically (fixed-order tree)
        if (warp == 0) {
            float v = 0.f;
#pragma unroll
            for (int b = lane; b < GRID; b += 32) v += __ldcg(&g_partial[cur][b]);
            v = warp_sum(v);
            if (lane == 0) s_z = v;
        }
        __syncthreads();
        float Z = s_z;
        invZ = 1.0f / Z;
        if (bid == 0 && tid == 0) lik += (double)logf(Z);
    }

    if (bid == 0 && tid == 0) out[0] = (float)lik;
}

// ---------------- launch ----------------
extern "C" void kernel_launch(void* const* d_in, const int* in_sizes, int n_in,
                              void* d_out, int out_size) {
    const float* log_M0    = (const float*)d_in[0];
    const float* log_trans = (const float*)d_in[1];
    const float* log_emit  = (const float*)d_in[2];
    const int*   Tptr      = (const int*)d_in[3];
    float* out = (float*)d_out;

    hmm_prep_kernel<<<2048, 256>>>(log_trans);
    hmm_main_kernel<<<GRID, BLOCK>>>(log_M0, log_emit, Tptr, out);
}